// round 1
// baseline (speedup 1.0000x reference)
#include <cuda_runtime.h>
#include <math.h>

// Problem constants
#define LSEQ   512
#define BATCH  32
#define NIN    72
#define DDIM   512
#define NOUTC  144
#define NLAYER 5
#define MROWS  (LSEQ*BATCH)   // 16384
#define D2     (2*DDIM)       // 1024

// Scratch (device globals — no allocation allowed)
__device__ float g_y [MROWS*D2];          // 67 MB
__device__ float g_xn[MROWS*D2];          // 67 MB
__device__ float g_U [MROWS*4*D2];        // 268 MB (largest U: k=4 layer)
__device__ float g_h [MROWS*D2];          // 67 MB

// ---------------------------------------------------------------------------
// Classic SGEMM: C[M,N] = A[M,K] @ B[K,N] (+bias) (+relu)
// 128x128 block tile, BK=8, 256 threads, 8x8 per-thread tile.
// Requires K % 8 == 0 (true: 72, 512, 1024). N guarded (for N=144).
// ---------------------------------------------------------------------------
#define BM 128
#define BN 128
#define BK 8

__global__ __launch_bounds__(256) void sgemm_kernel(
    const float* __restrict__ A, const float* __restrict__ B,
    const float* __restrict__ bias, float* __restrict__ C,
    int M, int N, int K, int relu)
{
    __shared__ float As[BK][BM];
    __shared__ float Bs[BK][BN];

    const int tid = threadIdx.x;
    const int bm  = blockIdx.y * BM;
    const int bn  = blockIdx.x * BN;
    const int tx  = tid & 15;
    const int ty  = tid >> 4;

    const int arow = tid >> 1;          // 0..127
    const int acol = (tid & 1) * 4;     // 0 or 4
    const int brow = tid >> 5;          // 0..7
    const int bcol = (tid & 31) * 4;    // 0..124

    float acc[8][8];
    #pragma unroll
    for (int i = 0; i < 8; i++)
        #pragma unroll
        for (int j = 0; j < 8; j++) acc[i][j] = 0.f;

    for (int k0 = 0; k0 < K; k0 += BK) {
        // Load A tile (transposed into As)
        float4 av = *(const float4*)(A + (size_t)(bm + arow) * K + k0 + acol);
        As[acol + 0][arow] = av.x;
        As[acol + 1][arow] = av.y;
        As[acol + 2][arow] = av.z;
        As[acol + 3][arow] = av.w;

        // Load B tile (guard columns for N=144)
        float4 bv = make_float4(0.f, 0.f, 0.f, 0.f);
        int gc = bn + bcol;
        const float* bp = B + (size_t)(k0 + brow) * N;
        if (gc + 3 < N) {
            bv = *(const float4*)(bp + gc);
        } else {
            if (gc     < N) bv.x = bp[gc];
            if (gc + 1 < N) bv.y = bp[gc + 1];
            if (gc + 2 < N) bv.z = bp[gc + 2];
            if (gc + 3 < N) bv.w = bp[gc + 3];
        }
        *(float4*)&Bs[brow][bcol] = bv;

        __syncthreads();

        #pragma unroll
        for (int kk = 0; kk < BK; kk++) {
            float ar[8], br[8];
            *(float4*)&ar[0] = *(const float4*)&As[kk][ty * 8];
            *(float4*)&ar[4] = *(const float4*)&As[kk][ty * 8 + 4];
            *(float4*)&br[0] = *(const float4*)&Bs[kk][tx * 8];
            *(float4*)&br[4] = *(const float4*)&Bs[kk][tx * 8 + 4];
            #pragma unroll
            for (int i = 0; i < 8; i++)
                #pragma unroll
                for (int j = 0; j < 8; j++)
                    acc[i][j] += ar[i] * br[j];
        }
        __syncthreads();
    }

    #pragma unroll
    for (int i = 0; i < 8; i++) {
        int row = bm + ty * 8 + i;
        #pragma unroll
        for (int j = 0; j < 8; j++) {
            int col = bn + tx * 8 + j;
            if (col < N) {
                float v = acc[i][j];
                if (bias) v += bias[col];
                if (relu) v = fmaxf(v, 0.f);
                C[(size_t)row * N + col] = v;
            }
        }
    }
}

// ---------------------------------------------------------------------------
// LayerNorm over last dim W (512 or 1024), one block per row.
// ---------------------------------------------------------------------------
__global__ __launch_bounds__(256) void layernorm_kernel(
    const float* __restrict__ in, const float* __restrict__ gw,
    const float* __restrict__ bw, float* __restrict__ outp, int W)
{
    const int row = blockIdx.x;
    const float* xr = in + (size_t)row * W;

    float s = 0.f, s2 = 0.f;
    for (int i = threadIdx.x; i < W; i += blockDim.x) {
        float v = xr[i];
        s  += v;
        s2 += v * v;
    }

    __shared__ float sh0[8], sh1[8];
    #pragma unroll
    for (int o = 16; o; o >>= 1) {
        s  += __shfl_xor_sync(0xFFFFFFFFu, s,  o);
        s2 += __shfl_xor_sync(0xFFFFFFFFu, s2, o);
    }
    const int w  = threadIdx.x >> 5;
    const int ln = threadIdx.x & 31;
    if (ln == 0) { sh0[w] = s; sh1[w] = s2; }
    __syncthreads();
    if (threadIdx.x < 32) {
        s  = (ln < 8) ? sh0[ln] : 0.f;
        s2 = (ln < 8) ? sh1[ln] : 0.f;
        #pragma unroll
        for (int o = 4; o; o >>= 1) {
            s  += __shfl_xor_sync(0xFFFFFFFFu, s,  o);
            s2 += __shfl_xor_sync(0xFFFFFFFFu, s2, o);
        }
        if (ln == 0) { sh0[0] = s; sh1[0] = s2; }
    }
    __syncthreads();

    const float mean = sh0[0] / (float)W;
    const float var  = sh1[0] / (float)W - mean * mean;
    const float inv  = rsqrtf(var + 1e-5f);

    float* orow = outp + (size_t)row * W;
    for (int i = threadIdx.x; i < W; i += blockDim.x)
        orow[i] = (xr[i] - mean) * inv * gw[i] + bw[i];
}

// ---------------------------------------------------------------------------
// Bidirectional SRU scan. One thread per (dir, b, d) chain; 32768 threads.
// U layout: (L, B, 2, D, k) row-major (= natural GEMM output).
// k==4: res = U[...,3]; k==3: res = xn[t, b, dir*D + d] (xn width 2D).
// h output: (L, B, 2D), forward cols [0,D), backward cols [D,2D) at natural t.
// c_out: (B, 2D).
// ---------------------------------------------------------------------------
__device__ __forceinline__ float sigmf(float x) {
    return 1.f / (1.f + expf(-x));
}

__global__ __launch_bounds__(256) void sru_scan_kernel(
    const float* __restrict__ U, const float* __restrict__ xn,
    const float* __restrict__ wc, const float* __restrict__ bb,
    float* __restrict__ h, float* __restrict__ c_out, int k)
{
    const int idx = blockIdx.x * blockDim.x + threadIdx.x;   // < 2*B*D
    const int d   = idx % DDIM;
    const int b   = (idx / DDIM) % BATCH;
    const int dir = idx / (BATCH * DDIM);

    // wc/bb shape (2 gates, 2 dirs, D)
    const float wcf = wc[(0 * 2 + dir) * DDIM + d];
    const float wcr = wc[(1 * 2 + dir) * DDIM + d];
    const float bf  = bb[(0 * 2 + dir) * DDIM + d];
    const float br  = bb[(1 * 2 + dir) * DDIM + d];

    const int colbase = (dir * DDIM + d) * k;
    const int rowlen  = 2 * DDIM * k;
    const int hcol    = dir * DDIM + d;

    float c = 0.f;
    for (int s = 0; s < LSEQ; s++) {
        const int t = dir ? (LSEQ - 1 - s) : s;
        const float* up = U + (size_t)(t * BATCH + b) * rowlen + colbase;
        float u0, u1, u2, res;
        if (k == 4) {
            float4 v = *(const float4*)up;
            u0 = v.x; u1 = v.y; u2 = v.z; res = v.w;
        } else {
            u0 = up[0]; u1 = up[1]; u2 = up[2];
            res = xn[(size_t)(t * BATCH + b) * D2 + hcol];
        }
        float f = sigmf(u1 + wcf * c + bf);
        c = f * c + (1.f - f) * u0;
        float r = sigmf(u2 + wcr * c + br);
        h[(size_t)(t * BATCH + b) * D2 + hcol] = r * c + (1.f - r) * res;
    }
    c_out[(size_t)b * D2 + hcol] = c;
}

// ---------------------------------------------------------------------------
// Launch
// ---------------------------------------------------------------------------
extern "C" void kernel_launch(void* const* d_in, const int* in_sizes, int n_in,
                              void* d_out, int out_size)
{
    const float* x      = (const float*)d_in[0];
    const float* lin1_w = (const float*)d_in[1];
    const float* lin1_b = (const float*)d_in[2];
    const float* lin2_w = (const float*)d_in[3];
    const float* lin2_b = (const float*)d_in[4];
    const float* W0     = (const float*)d_in[5];
    const float* wc0    = (const float*)d_in[6];
    const float* b0     = (const float*)d_in[7];
    const float* ln0_g  = (const float*)d_in[8];
    const float* ln0_b  = (const float*)d_in[9];
    const float* Wl     = (const float*)d_in[10];
    const float* wcl    = (const float*)d_in[11];
    const float* bl     = (const float*)d_in[12];
    const float* lnl_g  = (const float*)d_in[13];
    const float* lnl_b  = (const float*)d_in[14];
    float* out = (float*)d_out;

    float *py, *pxn, *pU, *ph;
    cudaGetSymbolAddress((void**)&py,  g_y);
    cudaGetSymbolAddress((void**)&pxn, g_xn);
    cudaGetSymbolAddress((void**)&pU,  g_U);
    cudaGetSymbolAddress((void**)&ph,  g_h);

    const size_t OUT0 = (size_t)MROWS * NOUTC;   // start of cs region

    // lin1 + relu: (16384,72) @ (72,512)
    sgemm_kernel<<<dim3(DDIM / BN, MROWS / BM), 256>>>(
        x, lin1_w, lin1_b, py, MROWS, DDIM, NIN, 1);

    float* cur = py;
    float* nxt = ph;
    for (int li = 0; li < NLAYER; li++) {
        const int   Din = (li == 0) ? DDIM : D2;
        const int   k   = (li == 0) ? 4 : 3;
        const int   Nou = 2 * DDIM * k;                       // 4096 or 3072
        const float* g  = (li == 0) ? ln0_g : lnl_g + (size_t)(li - 1) * D2;
        const float* be = (li == 0) ? ln0_b : lnl_b + (size_t)(li - 1) * D2;
        const float* W  = (li == 0) ? W0    : Wl    + (size_t)(li - 1) * D2 * 3 * D2;
        const float* wc = (li == 0) ? wc0   : wcl   + (size_t)(li - 1) * 2 * 2 * DDIM;
        const float* bg = (li == 0) ? b0    : bl    + (size_t)(li - 1) * 2 * 2 * DDIM;

        layernorm_kernel<<<MROWS, 256>>>(cur, g, be, pxn, Din);
        sgemm_kernel<<<dim3(Nou / BN, MROWS / BM), 256>>>(
            pxn, W, nullptr, pU, MROWS, Nou, Din, 0);
        sru_scan_kernel<<<(2 * BATCH * DDIM) / 256, 256>>>(
            pU, pxn, wc, bg, nxt, out + OUT0 + (size_t)li * BATCH * D2, k);

        float* t = cur; cur = nxt; nxt = t;
    }

    // lin2: (16384,1024) @ (1024,144) -> out
    sgemm_kernel<<<dim3((NOUTC + BN - 1) / BN, MROWS / BM), 256>>>(
        cur, lin2_w, lin2_b, out, MROWS, NOUTC, D2, 0);
}

// round 3
// speedup vs baseline: 2.0514x; 2.0514x over previous
#include <cuda_runtime.h>
#include <math.h>
#include <stdint.h>

// Problem constants
#define LSEQ   512
#define BATCH  32
#define NIN    72
#define DDIM   512
#define NOUTC  144
#define NLAYER 5
#define MROWS  (LSEQ*BATCH)   // 16384
#define D2     (2*DDIM)       // 1024

// Scratch (device globals — no allocation allowed)
__device__ float g_y [MROWS*D2];
__device__ float g_xn[MROWS*D2];
__device__ float g_U [MROWS*4*D2];
__device__ float g_h [MROWS*D2];

// ---------------------------------------------------------------------------
// Helpers
// ---------------------------------------------------------------------------
__device__ __forceinline__ uint32_t smem_u32(const void* p) {
    uint32_t a;
    asm("{ .reg .u64 t; cvta.to.shared.u64 t, %1; cvt.u32.u64 %0, t; }"
        : "=r"(a) : "l"(p));
    return a;
}
__device__ __forceinline__ uint32_t f2tf32(float f) {
    uint32_t u; asm("cvt.rna.tf32.f32 %0, %1;" : "=r"(u) : "f"(f)); return u;
}
__device__ __forceinline__ void cp16(uint32_t s, const void* g) {
    asm volatile("cp.async.cg.shared.global [%0], [%1], 16;" :: "r"(s), "l"(g));
}

// ---------------------------------------------------------------------------
// TF32 tensor-core GEMM via mma.sync (sm_80+ path, works on plain sm_103):
// C[M,N] = A[M,K] @ B[K,N], fp32 in/out, tf32 multiply, fp32 accumulate.
// 128x128 CTA tile, BK=32, 256 threads, warp grid 2(M)x4(N), warp tile 64x32.
// Requires: M%128==0, N%128==0, K%32==0.
// Smem: A[128][36] x2, B[32][136] x2 (pads chosen for conflict-free frag LDS).
// ---------------------------------------------------------------------------
#define TBM 128
#define TBN 128
#define TBK 32
#define ASTRIDE 36
#define BSTRIDE 136
#define ABYTES (TBM*ASTRIDE*4)     // 18432
#define BBYTES (TBK*BSTRIDE*4)     // 17408
#define TSMEM  (2*ABYTES + 2*BBYTES) // 71680

__global__ __launch_bounds__(256) void gemm_tf32_mma_kernel(
    const float* __restrict__ A, const float* __restrict__ B,
    float* __restrict__ C, int N, int K)
{
    extern __shared__ char smem[];
    const uint32_t sb = smem_u32(smem);
    const int tid  = threadIdx.x;
    const int w    = tid >> 5;
    const int lane = tid & 31;
    const int wm   = w & 1;        // 0..1  (M)
    const int wn   = w >> 1;       // 0..3  (N)
    const int bm   = blockIdx.y * TBM;
    const int bn   = blockIdx.x * TBN;

    const uint32_t sA[2] = { sb,              sb + ABYTES };
    const uint32_t sB[2] = { sb + 2*ABYTES,   sb + 2*ABYTES + BBYTES };
    float* fA[2]; float* fB[2];
    fA[0] = (float*)smem;                fA[1] = (float*)(smem + ABYTES);
    fB[0] = (float*)(smem + 2*ABYTES);   fB[1] = (float*)(smem + 2*ABYTES + BBYTES);

    float acc[4][4][4];
    #pragma unroll
    for (int i = 0; i < 4; i++)
        #pragma unroll
        for (int j = 0; j < 4; j++)
            #pragma unroll
            for (int r = 0; r < 4; r++) acc[i][j][r] = 0.f;

    const int nc = K / TBK;

    // ---- async load of one K-chunk into buffer s ----
    auto load_chunk = [&](int ch, int s) {
        const int k0 = ch * TBK;
        // A: 128 rows x 32 floats = 1024 float4, 4 per thread
        #pragma unroll
        for (int i = 0; i < 4; i++) {
            int idx = tid + i * 256;
            int row = idx >> 3, q = idx & 7;
            cp16(sA[s] + (row * ASTRIDE + q * 4) * 4,
                 A + (size_t)(bm + row) * K + k0 + q * 4);
        }
        // B: 32 rows x 128 floats = 1024 float4, 4 per thread
        #pragma unroll
        for (int i = 0; i < 4; i++) {
            int idx = tid + i * 256;
            int row = idx >> 5, q = idx & 31;
            cp16(sB[s] + (row * BSTRIDE + q * 4) * 4,
                 B + (size_t)(k0 + row) * N + bn + q * 4);
        }
    };

    load_chunk(0, 0);
    asm volatile("cp.async.commit_group;" ::: "memory");

    for (int ch = 0; ch < nc; ch++) {
        const int s = ch & 1;
        if (ch + 1 < nc) load_chunk(ch + 1, s ^ 1);
        asm volatile("cp.async.commit_group;" ::: "memory");
        asm volatile("cp.async.wait_group 1;" ::: "memory");
        __syncthreads();

        const float* as = fA[s];
        const float* bs = fB[s];
        #pragma unroll
        for (int kk = 0; kk < 4; kk++) {
            const int kb = kk * 8;
            uint32_t af[4][4], bf[4][2];
            #pragma unroll
            for (int mi = 0; mi < 4; mi++) {
                int rowb = wm * 64 + mi * 16 + (lane >> 2);
                const float* p = as + rowb * ASTRIDE + kb + (lane & 3);
                af[mi][0] = f2tf32(p[0]);
                af[mi][1] = f2tf32(p[8 * ASTRIDE]);
                af[mi][2] = f2tf32(p[4]);
                af[mi][3] = f2tf32(p[8 * ASTRIDE + 4]);
            }
            #pragma unroll
            for (int ni = 0; ni < 4; ni++) {
                int colb = wn * 32 + ni * 8 + (lane >> 2);
                const float* p = bs + (kb + (lane & 3)) * BSTRIDE + colb;
                bf[ni][0] = f2tf32(p[0]);
                bf[ni][1] = f2tf32(p[4 * BSTRIDE]);
            }
            #pragma unroll
            for (int mi = 0; mi < 4; mi++)
                #pragma unroll
                for (int ni = 0; ni < 4; ni++) {
                    asm volatile(
                        "mma.sync.aligned.m16n8k8.row.col.f32.tf32.tf32.f32 "
                        "{%0,%1,%2,%3}, {%4,%5,%6,%7}, {%8,%9}, {%0,%1,%2,%3};"
                        : "+f"(acc[mi][ni][0]), "+f"(acc[mi][ni][1]),
                          "+f"(acc[mi][ni][2]), "+f"(acc[mi][ni][3])
                        : "r"(af[mi][0]), "r"(af[mi][1]),
                          "r"(af[mi][2]), "r"(af[mi][3]),
                          "r"(bf[ni][0]), "r"(bf[ni][1]));
                }
        }
        __syncthreads();
    }

    // Epilogue
    #pragma unroll
    for (int mi = 0; mi < 4; mi++) {
        const size_t r0 = (size_t)bm + wm * 64 + mi * 16 + (lane >> 2);
        #pragma unroll
        for (int ni = 0; ni < 4; ni++) {
            const int col = bn + wn * 32 + ni * 8 + (lane & 3) * 2;
            float2 v0 = make_float2(acc[mi][ni][0], acc[mi][ni][1]);
            float2 v1 = make_float2(acc[mi][ni][2], acc[mi][ni][3]);
            *(float2*)(C + r0 * N + col)       = v0;
            *(float2*)(C + (r0 + 8) * N + col) = v1;
        }
    }
}

// ---------------------------------------------------------------------------
// Classic SGEMM (kept for lin1 K=72 and lin2 N=144)
// ---------------------------------------------------------------------------
#define BM 128
#define BN 128
#define BK 8

__global__ __launch_bounds__(256) void sgemm_kernel(
    const float* __restrict__ A, const float* __restrict__ B,
    const float* __restrict__ bias, float* __restrict__ C,
    int M, int N, int K, int relu)
{
    __shared__ float As[BK][BM];
    __shared__ float Bs[BK][BN];

    const int tid = threadIdx.x;
    const int bm  = blockIdx.y * BM;
    const int bn  = blockIdx.x * BN;
    const int tx  = tid & 15;
    const int ty  = tid >> 4;

    const int arow = tid >> 1;
    const int acol = (tid & 1) * 4;
    const int brow = tid >> 5;
    const int bcol = (tid & 31) * 4;

    float acc[8][8];
    #pragma unroll
    for (int i = 0; i < 8; i++)
        #pragma unroll
        for (int j = 0; j < 8; j++) acc[i][j] = 0.f;

    for (int k0 = 0; k0 < K; k0 += BK) {
        float4 av = *(const float4*)(A + (size_t)(bm + arow) * K + k0 + acol);
        As[acol + 0][arow] = av.x;
        As[acol + 1][arow] = av.y;
        As[acol + 2][arow] = av.z;
        As[acol + 3][arow] = av.w;

        float4 bv = make_float4(0.f, 0.f, 0.f, 0.f);
        int gc = bn + bcol;
        const float* bp = B + (size_t)(k0 + brow) * N;
        if (gc + 3 < N) {
            bv = *(const float4*)(bp + gc);
        } else {
            if (gc     < N) bv.x = bp[gc];
            if (gc + 1 < N) bv.y = bp[gc + 1];
            if (gc + 2 < N) bv.z = bp[gc + 2];
            if (gc + 3 < N) bv.w = bp[gc + 3];
        }
        *(float4*)&Bs[brow][bcol] = bv;

        __syncthreads();

        #pragma unroll
        for (int kk = 0; kk < BK; kk++) {
            float ar[8], br[8];
            *(float4*)&ar[0] = *(const float4*)&As[kk][ty * 8];
            *(float4*)&ar[4] = *(const float4*)&As[kk][ty * 8 + 4];
            *(float4*)&br[0] = *(const float4*)&Bs[kk][tx * 8];
            *(float4*)&br[4] = *(const float4*)&Bs[kk][tx * 8 + 4];
            #pragma unroll
            for (int i = 0; i < 8; i++)
                #pragma unroll
                for (int j = 0; j < 8; j++)
                    acc[i][j] += ar[i] * br[j];
        }
        __syncthreads();
    }

    #pragma unroll
    for (int i = 0; i < 8; i++) {
        int row = bm + ty * 8 + i;
        #pragma unroll
        for (int j = 0; j < 8; j++) {
            int col = bn + tx * 8 + j;
            if (col < N) {
                float v = acc[i][j];
                if (bias) v += bias[col];
                if (relu) v = fmaxf(v, 0.f);
                C[(size_t)row * N + col] = v;
            }
        }
    }
}

// ---------------------------------------------------------------------------
// LayerNorm over last dim W (512 or 1024), one block per row.
// ---------------------------------------------------------------------------
__global__ __launch_bounds__(256) void layernorm_kernel(
    const float* __restrict__ in, const float* __restrict__ gw,
    const float* __restrict__ bw, float* __restrict__ outp, int W)
{
    const int row = blockIdx.x;
    const float* xr = in + (size_t)row * W;

    float s = 0.f, s2 = 0.f;
    for (int i = threadIdx.x; i < W; i += blockDim.x) {
        float v = xr[i];
        s  += v;
        s2 += v * v;
    }

    __shared__ float sh0[8], sh1[8];
    #pragma unroll
    for (int o = 16; o; o >>= 1) {
        s  += __shfl_xor_sync(0xFFFFFFFFu, s,  o);
        s2 += __shfl_xor_sync(0xFFFFFFFFu, s2, o);
    }
    const int wq = threadIdx.x >> 5;
    const int ln = threadIdx.x & 31;
    if (ln == 0) { sh0[wq] = s; sh1[wq] = s2; }
    __syncthreads();
    if (threadIdx.x < 32) {
        s  = (ln < 8) ? sh0[ln] : 0.f;
        s2 = (ln < 8) ? sh1[ln] : 0.f;
        #pragma unroll
        for (int o = 4; o; o >>= 1) {
            s  += __shfl_xor_sync(0xFFFFFFFFu, s,  o);
            s2 += __shfl_xor_sync(0xFFFFFFFFu, s2, o);
        }
        if (ln == 0) { sh0[0] = s; sh1[0] = s2; }
    }
    __syncthreads();

    const float mean = sh0[0] / (float)W;
    const float var  = sh1[0] / (float)W - mean * mean;
    const float inv  = rsqrtf(var + 1e-5f);

    float* orow = outp + (size_t)row * W;
    for (int i = threadIdx.x; i < W; i += blockDim.x)
        orow[i] = (xr[i] - mean) * inv * gw[i] + bw[i];
}

// ---------------------------------------------------------------------------
// Bidirectional SRU scan with 4-deep prefetch ring.
// ---------------------------------------------------------------------------
__device__ __forceinline__ float sigmf(float x) {
    return 1.f / (1.f + expf(-x));
}

__global__ __launch_bounds__(256) void sru_scan_kernel(
    const float* __restrict__ U, const float* __restrict__ xn,
    const float* __restrict__ wc, const float* __restrict__ bb,
    float* __restrict__ h, float* __restrict__ c_out, int k)
{
    const int idx = blockIdx.x * blockDim.x + threadIdx.x;
    const int d   = idx % DDIM;
    const int b   = (idx / DDIM) % BATCH;
    const int dir = idx / (BATCH * DDIM);

    const float wcf = wc[(0 * 2 + dir) * DDIM + d];
    const float wcr = wc[(1 * 2 + dir) * DDIM + d];
    const float bf  = bb[(0 * 2 + dir) * DDIM + d];
    const float br  = bb[(1 * 2 + dir) * DDIM + d];

    const int hcol = dir * DDIM + d;
    const int t0   = dir ? (LSEQ - 1) : 0;
    float c = 0.f;

    if (k == 4) {
        const float4* U4 = (const float4*)U;
        long long i4 = ((long long)t0 * BATCH + b) * D2 + hcol;
        long long s4 = dir ? -(long long)(BATCH * D2) : (long long)(BATCH * D2);
        long long ih = i4;

        float4 buf[4];
        #pragma unroll
        for (int p = 0; p < 4; p++) buf[p] = U4[i4 + p * s4];

        for (int s = 0; s < LSEQ; s++) {
            float4 v = buf[s & 3];
            if (s + 4 < LSEQ) buf[s & 3] = U4[i4 + (long long)(s + 4) * s4];
            float f = sigmf(v.y + wcf * c + bf);
            c = f * c + (1.f - f) * v.x;
            float r = sigmf(v.z + wcr * c + br);
            h[ih] = r * c + (1.f - r) * v.w;
            ih += s4;
        }
    } else {
        long long iu = ((long long)t0 * BATCH + b) * (3 * D2) + hcol * 3;
        long long su = dir ? -(long long)(BATCH * 3 * D2) : (long long)(BATCH * 3 * D2);
        long long ix = ((long long)t0 * BATCH + b) * D2 + hcol;
        long long sx = dir ? -(long long)(BATCH * D2) : (long long)(BATCH * D2);

        float b0a[4], b1a[4], b2a[4], bra[4];
        #pragma unroll
        for (int p = 0; p < 4; p++) {
            const float* up = U + iu + p * su;
            b0a[p] = up[0]; b1a[p] = up[1]; b2a[p] = up[2];
            bra[p] = xn[ix + p * sx];
        }

        long long ih = ix;
        for (int s = 0; s < LSEQ; s++) {
            float u0 = b0a[s & 3], u1 = b1a[s & 3], u2 = b2a[s & 3], res = bra[s & 3];
            if (s + 4 < LSEQ) {
                const float* up = U + iu + (long long)(s + 4) * su;
                b0a[s & 3] = up[0]; b1a[s & 3] = up[1]; b2a[s & 3] = up[2];
                bra[s & 3] = xn[ix + (long long)(s + 4) * sx];
            }
            float f = sigmf(u1 + wcf * c + bf);
            c = f * c + (1.f - f) * u0;
            float r = sigmf(u2 + wcr * c + br);
            h[ih] = r * c + (1.f - r) * res;
            ih += sx;
        }
    }
    c_out[(size_t)b * D2 + hcol] = c;
}

// ---------------------------------------------------------------------------
// Launch
// ---------------------------------------------------------------------------
extern "C" void kernel_launch(void* const* d_in, const int* in_sizes, int n_in,
                              void* d_out, int out_size)
{
    const float* x      = (const float*)d_in[0];
    const float* lin1_w = (const float*)d_in[1];
    const float* lin1_b = (const float*)d_in[2];
    const float* lin2_w = (const float*)d_in[3];
    const float* lin2_b = (const float*)d_in[4];
    const float* W0     = (const float*)d_in[5];
    const float* wc0    = (const float*)d_in[6];
    const float* b0     = (const float*)d_in[7];
    const float* ln0_g  = (const float*)d_in[8];
    const float* ln0_b  = (const float*)d_in[9];
    const float* Wl     = (const float*)d_in[10];
    const float* wcl    = (const float*)d_in[11];
    const float* bl     = (const float*)d_in[12];
    const float* lnl_g  = (const float*)d_in[13];
    const float* lnl_b  = (const float*)d_in[14];
    float* out = (float*)d_out;

    float *py, *pxn, *pU, *ph;
    cudaGetSymbolAddress((void**)&py,  g_y);
    cudaGetSymbolAddress((void**)&pxn, g_xn);
    cudaGetSymbolAddress((void**)&pU,  g_U);
    cudaGetSymbolAddress((void**)&ph,  g_h);

    cudaFuncSetAttribute(gemm_tf32_mma_kernel,
                         cudaFuncAttributeMaxDynamicSharedMemorySize, TSMEM);

    const size_t OUT0 = (size_t)MROWS * NOUTC;

    // lin1 + relu: (16384,72) @ (72,512)
    sgemm_kernel<<<dim3(DDIM / BN, MROWS / BM), 256>>>(
        x, lin1_w, lin1_b, py, MROWS, DDIM, NIN, 1);

    float* cur = py;
    float* nxt = ph;
    for (int li = 0; li < NLAYER; li++) {
        const int   Din = (li == 0) ? DDIM : D2;
        const int   k   = (li == 0) ? 4 : 3;
        const int   Nou = 2 * DDIM * k;                       // 4096 or 3072
        const float* g  = (li == 0) ? ln0_g : lnl_g + (size_t)(li - 1) * D2;
        const float* be = (li == 0) ? ln0_b : lnl_b + (size_t)(li - 1) * D2;
        const float* W  = (li == 0) ? W0    : Wl    + (size_t)(li - 1) * D2 * 3 * D2;
        const float* wc = (li == 0) ? wc0   : wcl   + (size_t)(li - 1) * 2 * 2 * DDIM;
        const float* bg = (li == 0) ? b0    : bl    + (size_t)(li - 1) * 2 * 2 * DDIM;

        layernorm_kernel<<<MROWS, 256>>>(cur, g, be, pxn, Din);
        gemm_tf32_mma_kernel<<<dim3(Nou / TBN, MROWS / TBM), 256, TSMEM>>>(
            pxn, W, pU, Nou, Din);
        sru_scan_kernel<<<(2 * BATCH * DDIM) / 256, 256>>>(
            pU, pxn, wc, bg, nxt, out + OUT0 + (size_t)li * BATCH * D2, k);

        float* t = cur; cur = nxt; nxt = t;
    }

    // lin2: (16384,1024) @ (1024,144) -> out
    sgemm_kernel<<<dim3((NOUTC + BN - 1) / BN, MROWS / BM), 256>>>(
        cur, lin2_w, lin2_b, out, MROWS, NOUTC, D2, 0);
}

// round 4
// speedup vs baseline: 3.2136x; 1.5665x over previous
#include <cuda_runtime.h>
#include <math.h>
#include <stdint.h>

// Problem constants
#define LSEQ   512
#define BATCH  32
#define NIN    72
#define DDIM   512
#define NOUTC  144
#define NLAYER 5
#define MROWS  (LSEQ*BATCH)   // 16384
#define D2     (2*DDIM)       // 1024

// Scratch (device globals — no allocation allowed)
__device__ float g_y [MROWS*D2];          // layer ping
__device__ float g_xn[MROWS*D2];          // LN output fp32 (scan residual)
__device__ float g_xt[MROWS*D2];          // LN output tf32-rounded bits (GEMM A)
__device__ float g_U [MROWS*4*D2];        // GEMM output
__device__ float g_h [MROWS*D2];          // layer pong
#define WT_W0_ELEMS (DDIM*4*D2)                   // 2,097,152
#define WT_WL_ELEMS ((NLAYER-1)*D2*3*D2)          // 12,582,912
__device__ float g_wt[WT_W0_ELEMS + WT_WL_ELEMS]; // tf32-rounded weights

// ---------------------------------------------------------------------------
// Helpers
// ---------------------------------------------------------------------------
__device__ __forceinline__ uint32_t smem_u32(const void* p) {
    uint32_t a;
    asm("{ .reg .u64 t; cvta.to.shared.u64 t, %1; cvt.u32.u64 %0, t; }"
        : "=r"(a) : "l"(p));
    return a;
}
__device__ __forceinline__ uint32_t f2tf32(float f) {
    uint32_t u; asm("cvt.rna.tf32.f32 %0, %1;" : "=r"(u) : "f"(f)); return u;
}
__device__ __forceinline__ void cp16(uint32_t s, const void* g) {
    asm volatile("cp.async.cg.shared.global [%0], [%1], 16;" :: "r"(s), "l"(g));
}

// ---------------------------------------------------------------------------
// Pre-round fp32 -> tf32 bits (vectorized), n4 = element count / 4
// ---------------------------------------------------------------------------
__global__ __launch_bounds__(256) void round_tf32_kernel(
    const float4* __restrict__ in, uint4* __restrict__ out, int n4)
{
    int i = blockIdx.x * blockDim.x + threadIdx.x;
    if (i < n4) {
        float4 v = in[i];
        uint4 t;
        t.x = f2tf32(v.x); t.y = f2tf32(v.y);
        t.z = f2tf32(v.z); t.w = f2tf32(v.w);
        out[i] = t;
    }
}

// ---------------------------------------------------------------------------
// TF32 tensor-core GEMM via mma.sync. Inputs are PRE-ROUNDED tf32 bit patterns
// stored in float arrays. 128x128 CTA tile, BK=32, 256 threads, 3-stage
// cp.async pipeline. Warp grid 2(M)x4(N), warp tile 64x32.
// Requires: M%128==0, N%128==0, K%32==0.
// ---------------------------------------------------------------------------
#define TBM 128
#define TBN 128
#define TBK 32
#define ASTRIDE 36
#define BSTRIDE 136
#define ABYTES (TBM*ASTRIDE*4)       // 18432
#define BBYTES (TBK*BSTRIDE*4)       // 17408
#define STAGEB (ABYTES + BBYTES)     // 35840
#define TSMEM  (3*STAGEB)            // 107520

__global__ __launch_bounds__(256) void gemm_tf32_mma_kernel(
    const float* __restrict__ A, const float* __restrict__ B,
    float* __restrict__ C, int N, int K)
{
    extern __shared__ char smem[];
    const uint32_t sb = smem_u32(smem);
    const int tid  = threadIdx.x;
    const int w    = tid >> 5;
    const int lane = tid & 31;
    const int wm   = w & 1;        // 0..1  (M)
    const int wn   = w >> 1;       // 0..3  (N)
    const int bm   = blockIdx.y * TBM;
    const int bn   = blockIdx.x * TBN;

    float acc[4][4][4];
    #pragma unroll
    for (int i = 0; i < 4; i++)
        #pragma unroll
        for (int j = 0; j < 4; j++)
            #pragma unroll
            for (int r = 0; r < 4; r++) acc[i][j][r] = 0.f;

    const int nc = K / TBK;

    auto load_chunk = [&](int ch, int s) {
        const int k0 = ch * TBK;
        const uint32_t sA = sb + s * STAGEB;
        const uint32_t sB = sA + ABYTES;
        #pragma unroll
        for (int i = 0; i < 4; i++) {
            int idx = tid + i * 256;
            int row = idx >> 3, q = idx & 7;
            cp16(sA + (row * ASTRIDE + q * 4) * 4,
                 A + (size_t)(bm + row) * K + k0 + q * 4);
        }
        #pragma unroll
        for (int i = 0; i < 4; i++) {
            int idx = tid + i * 256;
            int row = idx >> 5, q = idx & 31;
            cp16(sB + (row * BSTRIDE + q * 4) * 4,
                 B + (size_t)(k0 + row) * N + bn + q * 4);
        }
    };

    load_chunk(0, 0);
    asm volatile("cp.async.commit_group;" ::: "memory");
    if (nc > 1) load_chunk(1, 1);
    asm volatile("cp.async.commit_group;" ::: "memory");

    for (int ch = 0; ch < nc; ch++) {
        const int s = ch % 3;
        asm volatile("cp.async.wait_group 1;" ::: "memory");
        __syncthreads();

        const uint32_t* as = (const uint32_t*)(smem + s * STAGEB);
        const uint32_t* bs = (const uint32_t*)(smem + s * STAGEB + ABYTES);
        #pragma unroll
        for (int kk = 0; kk < 4; kk++) {
            const int kb = kk * 8;
            uint32_t af[4][4], bf[4][2];
            #pragma unroll
            for (int mi = 0; mi < 4; mi++) {
                int rowb = wm * 64 + mi * 16 + (lane >> 2);
                const uint32_t* p = as + rowb * ASTRIDE + kb + (lane & 3);
                af[mi][0] = p[0];
                af[mi][1] = p[8 * ASTRIDE];
                af[mi][2] = p[4];
                af[mi][3] = p[8 * ASTRIDE + 4];
            }
            #pragma unroll
            for (int ni = 0; ni < 4; ni++) {
                int colb = wn * 32 + ni * 8 + (lane >> 2);
                const uint32_t* p = bs + (kb + (lane & 3)) * BSTRIDE + colb;
                bf[ni][0] = p[0];
                bf[ni][1] = p[4 * BSTRIDE];
            }
            #pragma unroll
            for (int mi = 0; mi < 4; mi++)
                #pragma unroll
                for (int ni = 0; ni < 4; ni++) {
                    asm volatile(
                        "mma.sync.aligned.m16n8k8.row.col.f32.tf32.tf32.f32 "
                        "{%0,%1,%2,%3}, {%4,%5,%6,%7}, {%8,%9}, {%0,%1,%2,%3};"
                        : "+f"(acc[mi][ni][0]), "+f"(acc[mi][ni][1]),
                          "+f"(acc[mi][ni][2]), "+f"(acc[mi][ni][3])
                        : "r"(af[mi][0]), "r"(af[mi][1]),
                          "r"(af[mi][2]), "r"(af[mi][3]),
                          "r"(bf[ni][0]), "r"(bf[ni][1]));
                }
        }

        if (ch + 2 < nc) load_chunk(ch + 2, (ch + 2) % 3);
        asm volatile("cp.async.commit_group;" ::: "memory");
    }

    // Epilogue
    #pragma unroll
    for (int mi = 0; mi < 4; mi++) {
        const size_t r0 = (size_t)bm + wm * 64 + mi * 16 + (lane >> 2);
        #pragma unroll
        for (int ni = 0; ni < 4; ni++) {
            const int col = bn + wn * 32 + ni * 8 + (lane & 3) * 2;
            *(float2*)(C + r0 * N + col)       = make_float2(acc[mi][ni][0], acc[mi][ni][1]);
            *(float2*)(C + (r0 + 8) * N + col) = make_float2(acc[mi][ni][2], acc[mi][ni][3]);
        }
    }
}

// ---------------------------------------------------------------------------
// Classic SGEMM (lin1 K=72 and lin2 N=144)
// ---------------------------------------------------------------------------
#define BM 128
#define BN 128
#define BK 8

__global__ __launch_bounds__(256) void sgemm_kernel(
    const float* __restrict__ A, const float* __restrict__ B,
    const float* __restrict__ bias, float* __restrict__ C,
    int M, int N, int K, int relu)
{
    __shared__ float As[BK][BM];
    __shared__ float Bs[BK][BN];

    const int tid = threadIdx.x;
    const int bm  = blockIdx.y * BM;
    const int bn  = blockIdx.x * BN;
    const int tx  = tid & 15;
    const int ty  = tid >> 4;

    const int arow = tid >> 1;
    const int acol = (tid & 1) * 4;
    const int brow = tid >> 5;
    const int bcol = (tid & 31) * 4;

    float acc[8][8];
    #pragma unroll
    for (int i = 0; i < 8; i++)
        #pragma unroll
        for (int j = 0; j < 8; j++) acc[i][j] = 0.f;

    for (int k0 = 0; k0 < K; k0 += BK) {
        float4 av = *(const float4*)(A + (size_t)(bm + arow) * K + k0 + acol);
        As[acol + 0][arow] = av.x;
        As[acol + 1][arow] = av.y;
        As[acol + 2][arow] = av.z;
        As[acol + 3][arow] = av.w;

        float4 bv = make_float4(0.f, 0.f, 0.f, 0.f);
        int gc = bn + bcol;
        const float* bp = B + (size_t)(k0 + brow) * N;
        if (gc + 3 < N) {
            bv = *(const float4*)(bp + gc);
        } else {
            if (gc     < N) bv.x = bp[gc];
            if (gc + 1 < N) bv.y = bp[gc + 1];
            if (gc + 2 < N) bv.z = bp[gc + 2];
            if (gc + 3 < N) bv.w = bp[gc + 3];
        }
        *(float4*)&Bs[brow][bcol] = bv;

        __syncthreads();

        #pragma unroll
        for (int kk = 0; kk < BK; kk++) {
            float ar[8], br[8];
            *(float4*)&ar[0] = *(const float4*)&As[kk][ty * 8];
            *(float4*)&ar[4] = *(const float4*)&As[kk][ty * 8 + 4];
            *(float4*)&br[0] = *(const float4*)&Bs[kk][tx * 8];
            *(float4*)&br[4] = *(const float4*)&Bs[kk][tx * 8 + 4];
            #pragma unroll
            for (int i = 0; i < 8; i++)
                #pragma unroll
                for (int j = 0; j < 8; j++)
                    acc[i][j] += ar[i] * br[j];
        }
        __syncthreads();
    }

    #pragma unroll
    for (int i = 0; i < 8; i++) {
        int row = bm + ty * 8 + i;
        #pragma unroll
        for (int j = 0; j < 8; j++) {
            int col = bn + tx * 8 + j;
            if (col < N) {
                float v = acc[i][j];
                if (bias) v += bias[col];
                if (relu) v = fmaxf(v, 0.f);
                C[(size_t)row * N + col] = v;
            }
        }
    }
}

// ---------------------------------------------------------------------------
// LayerNorm over last dim W; writes fp32 output AND tf32-rounded copy.
// ---------------------------------------------------------------------------
__global__ __launch_bounds__(256) void layernorm_kernel(
    const float* __restrict__ in, const float* __restrict__ gw,
    const float* __restrict__ bw, float* __restrict__ outp,
    uint32_t* __restrict__ outt, int W)
{
    const int row = blockIdx.x;
    const float* xr = in + (size_t)row * W;

    float s = 0.f, s2 = 0.f;
    for (int i = threadIdx.x; i < W; i += blockDim.x) {
        float v = xr[i];
        s  += v;
        s2 += v * v;
    }

    __shared__ float sh0[8], sh1[8];
    #pragma unroll
    for (int o = 16; o; o >>= 1) {
        s  += __shfl_xor_sync(0xFFFFFFFFu, s,  o);
        s2 += __shfl_xor_sync(0xFFFFFFFFu, s2, o);
    }
    const int wq = threadIdx.x >> 5;
    const int ln = threadIdx.x & 31;
    if (ln == 0) { sh0[wq] = s; sh1[wq] = s2; }
    __syncthreads();
    if (threadIdx.x < 32) {
        s  = (ln < 8) ? sh0[ln] : 0.f;
        s2 = (ln < 8) ? sh1[ln] : 0.f;
        #pragma unroll
        for (int o = 4; o; o >>= 1) {
            s  += __shfl_xor_sync(0xFFFFFFFFu, s,  o);
            s2 += __shfl_xor_sync(0xFFFFFFFFu, s2, o);
        }
        if (ln == 0) { sh0[0] = s; sh1[0] = s2; }
    }
    __syncthreads();

    const float mean = sh0[0] / (float)W;
    const float var  = sh1[0] / (float)W - mean * mean;
    const float inv  = rsqrtf(var + 1e-5f);

    float*    orow = outp + (size_t)row * W;
    uint32_t* trow = outt + (size_t)row * W;
    for (int i = threadIdx.x; i < W; i += blockDim.x) {
        float v = (xr[i] - mean) * inv * gw[i] + bw[i];
        orow[i] = v;
        trow[i] = f2tf32(v);
    }
}

// ---------------------------------------------------------------------------
// Bidirectional SRU scan, 8-deep register prefetch (static indices).
// One thread per (dir, b, d) chain; 128 threads/block, 256 blocks.
// ---------------------------------------------------------------------------
__device__ __forceinline__ float sigmf(float x) {
    return 1.f / (1.f + expf(-x));
}

__global__ __launch_bounds__(128) void sru_scan_kernel(
    const float* __restrict__ U, const float* __restrict__ xn,
    const float* __restrict__ wc, const float* __restrict__ bb,
    float* __restrict__ h, float* __restrict__ c_out, int k)
{
    const int idx = blockIdx.x * blockDim.x + threadIdx.x;
    const int d   = idx % DDIM;
    const int b   = (idx / DDIM) % BATCH;
    const int dir = idx / (BATCH * DDIM);

    const float wcf = wc[(0 * 2 + dir) * DDIM + d];
    const float wcr = wc[(1 * 2 + dir) * DDIM + d];
    const float bf  = bb[(0 * 2 + dir) * DDIM + d];
    const float br  = bb[(1 * 2 + dir) * DDIM + d];

    const int hcol = dir * DDIM + d;
    const int t0   = dir ? (LSEQ - 1) : 0;
    float c = 0.f;

    if (k == 4) {
        const float4* U4 = (const float4*)U;
        const long long base = ((long long)t0 * BATCH + b) * D2 + hcol;
        const long long st   = dir ? -(long long)(BATCH * D2) : (long long)(BATCH * D2);
        long long ih = base;

        float4 buf[8];
        #pragma unroll
        for (int j = 0; j < 8; j++) buf[j] = __ldcs(U4 + base + j * st);

        for (int s = 0; s < LSEQ; s += 8) {
            #pragma unroll
            for (int j = 0; j < 8; j++) {
                float4 v = buf[j];
                if (s + 8 + j < LSEQ)
                    buf[j] = __ldcs(U4 + base + (long long)(s + 8 + j) * st);
                float f = sigmf(v.y + wcf * c + bf);
                c = f * c + (1.f - f) * v.x;
                float r = sigmf(v.z + wcr * c + br);
                h[ih] = r * c + (1.f - r) * v.w;
                ih += st;
            }
        }
    } else {
        const long long baseu = ((long long)t0 * BATCH + b) * (3 * D2) + hcol * 3;
        const long long su    = dir ? -(long long)(BATCH * 3 * D2) : (long long)(BATCH * 3 * D2);
        const long long basex = ((long long)t0 * BATCH + b) * D2 + hcol;
        const long long sx    = dir ? -(long long)(BATCH * D2) : (long long)(BATCH * D2);

        float b0a[8], b1a[8], b2a[8], bra[8];
        #pragma unroll
        for (int j = 0; j < 8; j++) {
            const float* up = U + baseu + j * su;
            b0a[j] = __ldcs(up);
            b1a[j] = __ldcs(up + 1);
            b2a[j] = __ldcs(up + 2);
            bra[j] = __ldcs(xn + basex + j * sx);
        }

        long long ih = basex;
        for (int s = 0; s < LSEQ; s += 8) {
            #pragma unroll
            for (int j = 0; j < 8; j++) {
                float u0 = b0a[j], u1 = b1a[j], u2 = b2a[j], res = bra[j];
                if (s + 8 + j < LSEQ) {
                    const float* up = U + baseu + (long long)(s + 8 + j) * su;
                    b0a[j] = __ldcs(up);
                    b1a[j] = __ldcs(up + 1);
                    b2a[j] = __ldcs(up + 2);
                    bra[j] = __ldcs(xn + basex + (long long)(s + 8 + j) * sx);
                }
                float f = sigmf(u1 + wcf * c + bf);
                c = f * c + (1.f - f) * u0;
                float r = sigmf(u2 + wcr * c + br);
                h[ih] = r * c + (1.f - r) * res;
                ih += sx;
            }
        }
    }
    c_out[(size_t)b * D2 + hcol] = c;
}

// ---------------------------------------------------------------------------
// Launch
// ---------------------------------------------------------------------------
extern "C" void kernel_launch(void* const* d_in, const int* in_sizes, int n_in,
                              void* d_out, int out_size)
{
    const float* x      = (const float*)d_in[0];
    const float* lin1_w = (const float*)d_in[1];
    const float* lin1_b = (const float*)d_in[2];
    const float* lin2_w = (const float*)d_in[3];
    const float* lin2_b = (const float*)d_in[4];
    const float* W0     = (const float*)d_in[5];
    const float* wc0    = (const float*)d_in[6];
    const float* b0     = (const float*)d_in[7];
    const float* ln0_g  = (const float*)d_in[8];
    const float* ln0_b  = (const float*)d_in[9];
    const float* Wl     = (const float*)d_in[10];
    const float* wcl    = (const float*)d_in[11];
    const float* bl     = (const float*)d_in[12];
    const float* lnl_g  = (const float*)d_in[13];
    const float* lnl_b  = (const float*)d_in[14];
    float* out = (float*)d_out;

    float *py, *pxn, *pxt, *pU, *ph, *pwt;
    cudaGetSymbolAddress((void**)&py,  g_y);
    cudaGetSymbolAddress((void**)&pxn, g_xn);
    cudaGetSymbolAddress((void**)&pxt, g_xt);
    cudaGetSymbolAddress((void**)&pU,  g_U);
    cudaGetSymbolAddress((void**)&ph,  g_h);
    cudaGetSymbolAddress((void**)&pwt, g_wt);

    cudaFuncSetAttribute(gemm_tf32_mma_kernel,
                         cudaFuncAttributeMaxDynamicSharedMemorySize, TSMEM);

    const size_t OUT0 = (size_t)MROWS * NOUTC;

    // Pre-round weights to tf32 (once per launch)
    {
        int n4 = WT_W0_ELEMS / 4;
        round_tf32_kernel<<<(n4 + 255) / 256, 256>>>(
            (const float4*)W0, (uint4*)pwt, n4);
        n4 = WT_WL_ELEMS / 4;
        round_tf32_kernel<<<(n4 + 255) / 256, 256>>>(
            (const float4*)Wl, (uint4*)(pwt + WT_W0_ELEMS), n4);
    }

    // lin1 + relu: (16384,72) @ (72,512)
    sgemm_kernel<<<dim3(DDIM / BN, MROWS / BM), 256>>>(
        x, lin1_w, lin1_b, py, MROWS, DDIM, NIN, 1);

    float* cur = py;
    float* nxt = ph;
    for (int li = 0; li < NLAYER; li++) {
        const int   Din = (li == 0) ? DDIM : D2;
        const int   k   = (li == 0) ? 4 : 3;
        const int   Nou = 2 * DDIM * k;                       // 4096 or 3072
        const float* g  = (li == 0) ? ln0_g : lnl_g + (size_t)(li - 1) * D2;
        const float* be = (li == 0) ? ln0_b : lnl_b + (size_t)(li - 1) * D2;
        const float* W  = (li == 0) ? pwt   : pwt + WT_W0_ELEMS + (size_t)(li - 1) * D2 * 3 * D2;
        const float* wc = (li == 0) ? wc0   : wcl   + (size_t)(li - 1) * 2 * 2 * DDIM;
        const float* bg = (li == 0) ? b0    : bl    + (size_t)(li - 1) * 2 * 2 * DDIM;

        layernorm_kernel<<<MROWS, 256>>>(cur, g, be, pxn, (uint32_t*)pxt, Din);
        gemm_tf32_mma_kernel<<<dim3(Nou / TBN, MROWS / TBM), 256, TSMEM>>>(
            pxt, W, pU, Nou, Din);
        sru_scan_kernel<<<(2 * BATCH * DDIM) / 128, 128>>>(
            pU, pxn, wc, bg, nxt, out + OUT0 + (size_t)li * BATCH * D2, k);

        float* t = cur; cur = nxt; nxt = t;
    }

    // lin2: (16384,1024) @ (1024,144) -> out
    sgemm_kernel<<<dim3((NOUTC + BN - 1) / BN, MROWS / BM), 256>>>(
        cur, lin2_w, lin2_b, out, MROWS, NOUTC, D2, 0);
}

// round 5
// speedup vs baseline: 3.7656x; 1.1718x over previous
#include <cuda_runtime.h>
#include <math.h>
#include <stdint.h>

// Problem constants
#define LSEQ   512
#define BATCH  32
#define NIN    72
#define DDIM   512
#define NOUTC  144
#define NLAYER 5
#define MROWS  (LSEQ*BATCH)   // 16384
#define D2     (2*DDIM)       // 1024

// Scratch (device globals — no allocation allowed)
__device__ float g_y [MROWS*D2];
__device__ float g_xn[MROWS*D2];
__device__ float g_xt[MROWS*D2];
__device__ float g_U [MROWS*4*D2];
__device__ float g_h [MROWS*D2];
#define WT_W0_ELEMS (DDIM*4*D2)
#define WT_WL_ELEMS ((NLAYER-1)*D2*3*D2)
__device__ float g_wt[WT_W0_ELEMS + WT_WL_ELEMS];

// ---------------------------------------------------------------------------
// Helpers
// ---------------------------------------------------------------------------
__device__ __forceinline__ uint32_t smem_u32(const void* p) {
    uint32_t a;
    asm("{ .reg .u64 t; cvta.to.shared.u64 t, %1; cvt.u32.u64 %0, t; }"
        : "=r"(a) : "l"(p));
    return a;
}
__device__ __forceinline__ uint32_t f2tf32(float f) {
    uint32_t u; asm("cvt.rna.tf32.f32 %0, %1;" : "=r"(u) : "f"(f)); return u;
}
__device__ __forceinline__ void cp16(uint32_t s, const void* g) {
    asm volatile("cp.async.cg.shared.global [%0], [%1], 16;" :: "r"(s), "l"(g));
}
// Fast sigmoid: MUFU ex2 + rcp (rel err ~2^-22, fine for 1e-3 budget)
__device__ __forceinline__ float sigmf(float x) {
    float e;
    asm("ex2.approx.ftz.f32 %0, %1;" : "=f"(e) : "f"(-1.44269504f * x));
    float r;
    asm("rcp.approx.ftz.f32 %0, %1;" : "=f"(r) : "f"(1.f + e));
    return r;
}

// ---------------------------------------------------------------------------
// Pre-round fp32 -> tf32 bits
// ---------------------------------------------------------------------------
__global__ __launch_bounds__(256) void round_tf32_kernel(
    const float4* __restrict__ in, uint4* __restrict__ out, int n4)
{
    int i = blockIdx.x * blockDim.x + threadIdx.x;
    if (i < n4) {
        float4 v = in[i];
        uint4 t;
        t.x = f2tf32(v.x); t.y = f2tf32(v.y);
        t.z = f2tf32(v.z); t.w = f2tf32(v.w);
        out[i] = t;
    }
}

// ---------------------------------------------------------------------------
// TF32 tensor-core GEMM via mma.sync (pre-rounded inputs).
// 128x128 CTA tile, BK=32, 128 threads (4 warps, 2x2 grid of 64x64 warp
// tiles), 3-stage cp.async pipeline, 2 CTAs/SM.
// Requires: M%128==0, N%128==0, K%32==0.
// ---------------------------------------------------------------------------
#define TBM 128
#define TBN 128
#define TBK 32
#define ASTRIDE 36
#define BSTRIDE 136
#define ABYTES (TBM*ASTRIDE*4)       // 18432
#define BBYTES (TBK*BSTRIDE*4)       // 17408
#define STAGEB (ABYTES + BBYTES)     // 35840
#define TSMEM  (3*STAGEB)            // 107520

__global__ __launch_bounds__(128) void gemm_tf32_mma_kernel(
    const float* __restrict__ A, const float* __restrict__ B,
    float* __restrict__ C, int N, int K)
{
    extern __shared__ char smem[];
    const uint32_t sb = smem_u32(smem);
    const int tid  = threadIdx.x;
    const int w    = tid >> 5;
    const int lane = tid & 31;
    const int wm   = w & 1;        // 0..1  (M)
    const int wn   = w >> 1;       // 0..1  (N)
    const int bm   = blockIdx.y * TBM;
    const int bn   = blockIdx.x * TBN;

    float acc[4][8][4];
    #pragma unroll
    for (int i = 0; i < 4; i++)
        #pragma unroll
        for (int j = 0; j < 8; j++)
            #pragma unroll
            for (int r = 0; r < 4; r++) acc[i][j][r] = 0.f;

    const int nc = K / TBK;

    auto load_chunk = [&](int ch, int s) {
        const int k0 = ch * TBK;
        const uint32_t sA = sb + s * STAGEB;
        const uint32_t sB = sA + ABYTES;
        #pragma unroll
        for (int i = 0; i < 8; i++) {
            int idx = tid + i * 128;
            int row = idx >> 3, q = idx & 7;
            cp16(sA + (row * ASTRIDE + q * 4) * 4,
                 A + (size_t)(bm + row) * K + k0 + q * 4);
        }
        #pragma unroll
        for (int i = 0; i < 8; i++) {
            int idx = tid + i * 128;
            int row = idx >> 5, q = idx & 31;
            cp16(sB + (row * BSTRIDE + q * 4) * 4,
                 B + (size_t)(k0 + row) * N + bn + q * 4);
        }
    };

    load_chunk(0, 0);
    asm volatile("cp.async.commit_group;" ::: "memory");
    if (nc > 1) load_chunk(1, 1);
    asm volatile("cp.async.commit_group;" ::: "memory");

    for (int ch = 0; ch < nc; ch++) {
        const int s = ch % 3;
        asm volatile("cp.async.wait_group 1;" ::: "memory");
        __syncthreads();

        const uint32_t* as = (const uint32_t*)(smem + s * STAGEB);
        const uint32_t* bs = (const uint32_t*)(smem + s * STAGEB + ABYTES);
        #pragma unroll
        for (int kk = 0; kk < 4; kk++) {
            const int kb = kk * 8;
            uint32_t af[4][4], bf[8][2];
            #pragma unroll
            for (int mi = 0; mi < 4; mi++) {
                int rowb = wm * 64 + mi * 16 + (lane >> 2);
                const uint32_t* p = as + rowb * ASTRIDE + kb + (lane & 3);
                af[mi][0] = p[0];
                af[mi][1] = p[8 * ASTRIDE];
                af[mi][2] = p[4];
                af[mi][3] = p[8 * ASTRIDE + 4];
            }
            #pragma unroll
            for (int ni = 0; ni < 8; ni++) {
                int colb = wn * 64 + ni * 8 + (lane >> 2);
                const uint32_t* p = bs + (kb + (lane & 3)) * BSTRIDE + colb;
                bf[ni][0] = p[0];
                bf[ni][1] = p[4 * BSTRIDE];
            }
            #pragma unroll
            for (int mi = 0; mi < 4; mi++)
                #pragma unroll
                for (int ni = 0; ni < 8; ni++) {
                    asm volatile(
                        "mma.sync.aligned.m16n8k8.row.col.f32.tf32.tf32.f32 "
                        "{%0,%1,%2,%3}, {%4,%5,%6,%7}, {%8,%9}, {%0,%1,%2,%3};"
                        : "+f"(acc[mi][ni][0]), "+f"(acc[mi][ni][1]),
                          "+f"(acc[mi][ni][2]), "+f"(acc[mi][ni][3])
                        : "r"(af[mi][0]), "r"(af[mi][1]),
                          "r"(af[mi][2]), "r"(af[mi][3]),
                          "r"(bf[ni][0]), "r"(bf[ni][1]));
                }
        }

        if (ch + 2 < nc) load_chunk(ch + 2, (ch + 2) % 3);
        asm volatile("cp.async.commit_group;" ::: "memory");
    }

    // Epilogue
    #pragma unroll
    for (int mi = 0; mi < 4; mi++) {
        const size_t r0 = (size_t)bm + wm * 64 + mi * 16 + (lane >> 2);
        #pragma unroll
        for (int ni = 0; ni < 8; ni++) {
            const int col = bn + wn * 64 + ni * 8 + (lane & 3) * 2;
            *(float2*)(C + r0 * N + col)       = make_float2(acc[mi][ni][0], acc[mi][ni][1]);
            *(float2*)(C + (r0 + 8) * N + col) = make_float2(acc[mi][ni][2], acc[mi][ni][3]);
        }
    }
}

// ---------------------------------------------------------------------------
// Classic SGEMM (lin1 K=72 and lin2 N=144)
// ---------------------------------------------------------------------------
#define BM 128
#define BN 128
#define BK 8

__global__ __launch_bounds__(256) void sgemm_kernel(
    const float* __restrict__ A, const float* __restrict__ B,
    const float* __restrict__ bias, float* __restrict__ C,
    int M, int N, int K, int relu)
{
    __shared__ float As[BK][BM];
    __shared__ float Bs[BK][BN];

    const int tid = threadIdx.x;
    const int bm  = blockIdx.y * BM;
    const int bn  = blockIdx.x * BN;
    const int tx  = tid & 15;
    const int ty  = tid >> 4;

    const int arow = tid >> 1;
    const int acol = (tid & 1) * 4;
    const int brow = tid >> 5;
    const int bcol = (tid & 31) * 4;

    float acc[8][8];
    #pragma unroll
    for (int i = 0; i < 8; i++)
        #pragma unroll
        for (int j = 0; j < 8; j++) acc[i][j] = 0.f;

    for (int k0 = 0; k0 < K; k0 += BK) {
        float4 av = *(const float4*)(A + (size_t)(bm + arow) * K + k0 + acol);
        As[acol + 0][arow] = av.x;
        As[acol + 1][arow] = av.y;
        As[acol + 2][arow] = av.z;
        As[acol + 3][arow] = av.w;

        float4 bv = make_float4(0.f, 0.f, 0.f, 0.f);
        int gc = bn + bcol;
        const float* bp = B + (size_t)(k0 + brow) * N;
        if (gc + 3 < N) {
            bv = *(const float4*)(bp + gc);
        } else {
            if (gc     < N) bv.x = bp[gc];
            if (gc + 1 < N) bv.y = bp[gc + 1];
            if (gc + 2 < N) bv.z = bp[gc + 2];
            if (gc + 3 < N) bv.w = bp[gc + 3];
        }
        *(float4*)&Bs[brow][bcol] = bv;

        __syncthreads();

        #pragma unroll
        for (int kk = 0; kk < BK; kk++) {
            float ar[8], br[8];
            *(float4*)&ar[0] = *(const float4*)&As[kk][ty * 8];
            *(float4*)&ar[4] = *(const float4*)&As[kk][ty * 8 + 4];
            *(float4*)&br[0] = *(const float4*)&Bs[kk][tx * 8];
            *(float4*)&br[4] = *(const float4*)&Bs[kk][tx * 8 + 4];
            #pragma unroll
            for (int i = 0; i < 8; i++)
                #pragma unroll
                for (int j = 0; j < 8; j++)
                    acc[i][j] += ar[i] * br[j];
        }
        __syncthreads();
    }

    #pragma unroll
    for (int i = 0; i < 8; i++) {
        int row = bm + ty * 8 + i;
        #pragma unroll
        for (int j = 0; j < 8; j++) {
            int col = bn + tx * 8 + j;
            if (col < N) {
                float v = acc[i][j];
                if (bias) v += bias[col];
                if (relu) v = fmaxf(v, 0.f);
                C[(size_t)row * N + col] = v;
            }
        }
    }
}

// ---------------------------------------------------------------------------
// One-pass LayerNorm, register-resident row. 128 threads, NV4 float4/thread.
// W = NV4*512. Writes fp32 + tf32-bits copies.
// ---------------------------------------------------------------------------
template<int NV4>
__global__ __launch_bounds__(128) void ln_kernel(
    const float4* __restrict__ in, const float4* __restrict__ gw,
    const float4* __restrict__ bw, float4* __restrict__ outp,
    uint4* __restrict__ outt)
{
    const int W4  = NV4 * 128;
    const int row = blockIdx.x;
    const int tid = threadIdx.x;

    float4 v[NV4];
    #pragma unroll
    for (int i = 0; i < NV4; i++)
        v[i] = in[(size_t)row * W4 + tid + i * 128];

    float s = 0.f, s2 = 0.f;
    #pragma unroll
    for (int i = 0; i < NV4; i++) {
        s  += v[i].x + v[i].y + v[i].z + v[i].w;
        s2 += v[i].x * v[i].x + v[i].y * v[i].y
            + v[i].z * v[i].z + v[i].w * v[i].w;
    }

    __shared__ float sh0[4], sh1[4];
    #pragma unroll
    for (int o = 16; o; o >>= 1) {
        s  += __shfl_xor_sync(0xFFFFFFFFu, s,  o);
        s2 += __shfl_xor_sync(0xFFFFFFFFu, s2, o);
    }
    const int wq = tid >> 5, ln = tid & 31;
    if (ln == 0) { sh0[wq] = s; sh1[wq] = s2; }
    __syncthreads();
    s  = sh0[0] + sh0[1] + sh0[2] + sh0[3];
    s2 = sh1[0] + sh1[1] + sh1[2] + sh1[3];

    const float Wf   = (float)(NV4 * 512);
    const float mean = s / Wf;
    const float var  = s2 / Wf - mean * mean;
    const float inv  = rsqrtf(var + 1e-5f);

    #pragma unroll
    for (int i = 0; i < NV4; i++) {
        float4 g = gw[tid + i * 128];
        float4 b = bw[tid + i * 128];
        float4 o;
        o.x = (v[i].x - mean) * inv * g.x + b.x;
        o.y = (v[i].y - mean) * inv * g.y + b.y;
        o.z = (v[i].z - mean) * inv * g.z + b.z;
        o.w = (v[i].w - mean) * inv * g.w + b.w;
        outp[(size_t)row * W4 + tid + i * 128] = o;
        uint4 t;
        t.x = f2tf32(o.x); t.y = f2tf32(o.y);
        t.z = f2tf32(o.z); t.w = f2tf32(o.w);
        outt[(size_t)row * W4 + tid + i * 128] = t;
    }
}

// ---------------------------------------------------------------------------
// Bidirectional SRU scan, 8-deep register prefetch, fast sigmoid.
// ---------------------------------------------------------------------------
__global__ __launch_bounds__(128) void sru_scan_kernel(
    const float* __restrict__ U, const float* __restrict__ xn,
    const float* __restrict__ wc, const float* __restrict__ bb,
    float* __restrict__ h, float* __restrict__ c_out, int k)
{
    const int idx = blockIdx.x * blockDim.x + threadIdx.x;
    const int d   = idx % DDIM;
    const int b   = (idx / DDIM) % BATCH;
    const int dir = idx / (BATCH * DDIM);

    const float wcf = wc[(0 * 2 + dir) * DDIM + d];
    const float wcr = wc[(1 * 2 + dir) * DDIM + d];
    const float bf  = bb[(0 * 2 + dir) * DDIM + d];
    const float br  = bb[(1 * 2 + dir) * DDIM + d];

    const int hcol = dir * DDIM + d;
    const int t0   = dir ? (LSEQ - 1) : 0;
    float c = 0.f;

    if (k == 4) {
        const float4* U4 = (const float4*)U;
        const long long base = ((long long)t0 * BATCH + b) * D2 + hcol;
        const long long st   = dir ? -(long long)(BATCH * D2) : (long long)(BATCH * D2);
        long long ih = base;

        float4 buf[8];
        #pragma unroll
        for (int j = 0; j < 8; j++) buf[j] = __ldcs(U4 + base + j * st);

        for (int s = 0; s < LSEQ; s += 8) {
            #pragma unroll
            for (int j = 0; j < 8; j++) {
                float4 v = buf[j];
                if (s + 8 + j < LSEQ)
                    buf[j] = __ldcs(U4 + base + (long long)(s + 8 + j) * st);
                float f = sigmf(v.y + wcf * c + bf);
                c = f * c + (1.f - f) * v.x;
                float r = sigmf(v.z + wcr * c + br);
                h[ih] = r * c + (1.f - r) * v.w;
                ih += st;
            }
        }
    } else {
        const long long baseu = ((long long)t0 * BATCH + b) * (3 * D2) + hcol * 3;
        const long long su    = dir ? -(long long)(BATCH * 3 * D2) : (long long)(BATCH * 3 * D2);
        const long long basex = ((long long)t0 * BATCH + b) * D2 + hcol;
        const long long sx    = dir ? -(long long)(BATCH * D2) : (long long)(BATCH * D2);

        float b0a[8], b1a[8], b2a[8], bra[8];
        #pragma unroll
        for (int j = 0; j < 8; j++) {
            const float* up = U + baseu + j * su;
            b0a[j] = __ldcs(up);
            b1a[j] = __ldcs(up + 1);
            b2a[j] = __ldcs(up + 2);
            bra[j] = __ldcs(xn + basex + j * sx);
        }

        long long ih = basex;
        for (int s = 0; s < LSEQ; s += 8) {
            #pragma unroll
            for (int j = 0; j < 8; j++) {
                float u0 = b0a[j], u1 = b1a[j], u2 = b2a[j], res = bra[j];
                if (s + 8 + j < LSEQ) {
                    const float* up = U + baseu + (long long)(s + 8 + j) * su;
                    b0a[j] = __ldcs(up);
                    b1a[j] = __ldcs(up + 1);
                    b2a[j] = __ldcs(up + 2);
                    bra[j] = __ldcs(xn + basex + (long long)(s + 8 + j) * sx);
                }
                float f = sigmf(u1 + wcf * c + bf);
                c = f * c + (1.f - f) * u0;
                float r = sigmf(u2 + wcr * c + br);
                h[ih] = r * c + (1.f - r) * res;
                ih += sx;
            }
        }
    }
    c_out[(size_t)b * D2 + hcol] = c;
}

// ---------------------------------------------------------------------------
// Launch
// ---------------------------------------------------------------------------
extern "C" void kernel_launch(void* const* d_in, const int* in_sizes, int n_in,
                              void* d_out, int out_size)
{
    const float* x      = (const float*)d_in[0];
    const float* lin1_w = (const float*)d_in[1];
    const float* lin1_b = (const float*)d_in[2];
    const float* lin2_w = (const float*)d_in[3];
    const float* lin2_b = (const float*)d_in[4];
    const float* W0     = (const float*)d_in[5];
    const float* wc0    = (const float*)d_in[6];
    const float* b0     = (const float*)d_in[7];
    const float* ln0_g  = (const float*)d_in[8];
    const float* ln0_b  = (const float*)d_in[9];
    const float* Wl     = (const float*)d_in[10];
    const float* wcl    = (const float*)d_in[11];
    const float* bl     = (const float*)d_in[12];
    const float* lnl_g  = (const float*)d_in[13];
    const float* lnl_b  = (const float*)d_in[14];
    float* out = (float*)d_out;

    float *py, *pxn, *pxt, *pU, *ph, *pwt;
    cudaGetSymbolAddress((void**)&py,  g_y);
    cudaGetSymbolAddress((void**)&pxn, g_xn);
    cudaGetSymbolAddress((void**)&pxt, g_xt);
    cudaGetSymbolAddress((void**)&pU,  g_U);
    cudaGetSymbolAddress((void**)&ph,  g_h);
    cudaGetSymbolAddress((void**)&pwt, g_wt);

    cudaFuncSetAttribute(gemm_tf32_mma_kernel,
                         cudaFuncAttributeMaxDynamicSharedMemorySize, TSMEM);

    const size_t OUT0 = (size_t)MROWS * NOUTC;

    // Pre-round weights to tf32
    {
        int n4 = WT_W0_ELEMS / 4;
        round_tf32_kernel<<<(n4 + 255) / 256, 256>>>(
            (const float4*)W0, (uint4*)pwt, n4);
        n4 = WT_WL_ELEMS / 4;
        round_tf32_kernel<<<(n4 + 255) / 256, 256>>>(
            (const float4*)Wl, (uint4*)(pwt + WT_W0_ELEMS), n4);
    }

    // lin1 + relu
    sgemm_kernel<<<dim3(DDIM / BN, MROWS / BM), 256>>>(
        x, lin1_w, lin1_b, py, MROWS, DDIM, NIN, 1);

    float* cur = py;
    float* nxt = ph;
    for (int li = 0; li < NLAYER; li++) {
        const int   Din = (li == 0) ? DDIM : D2;
        const int   k   = (li == 0) ? 4 : 3;
        const int   Nou = 2 * DDIM * k;
        const float* g  = (li == 0) ? ln0_g : lnl_g + (size_t)(li - 1) * D2;
        const float* be = (li == 0) ? ln0_b : lnl_b + (size_t)(li - 1) * D2;
        const float* W  = (li == 0) ? pwt   : pwt + WT_W0_ELEMS + (size_t)(li - 1) * D2 * 3 * D2;
        const float* wc = (li == 0) ? wc0   : wcl   + (size_t)(li - 1) * 2 * 2 * DDIM;
        const float* bg = (li == 0) ? b0    : bl    + (size_t)(li - 1) * 2 * 2 * DDIM;

        if (Din == DDIM)
            ln_kernel<1><<<MROWS, 128>>>(
                (const float4*)cur, (const float4*)g, (const float4*)be,
                (float4*)pxn, (uint4*)pxt);
        else
            ln_kernel<2><<<MROWS, 128>>>(
                (const float4*)cur, (const float4*)g, (const float4*)be,
                (float4*)pxn, (uint4*)pxt);

        gemm_tf32_mma_kernel<<<dim3(Nou / TBN, MROWS / TBM), 128, TSMEM>>>(
            pxt, W, pU, Nou, Din);
        sru_scan_kernel<<<(2 * BATCH * DDIM) / 128, 128>>>(
            pU, pxn, wc, bg, nxt, out + OUT0 + (size_t)li * BATCH * D2, k);

        float* t = cur; cur = nxt; nxt = t;
    }

    // lin2
    sgemm_kernel<<<dim3((NOUTC + BN - 1) / BN, MROWS / BM), 256>>>(
        cur, lin2_w, lin2_b, out, MROWS, NOUTC, D2, 0);
}